// round 14
// baseline (speedup 1.0000x reference)
#include <cuda_runtime.h>
#include <cuda_bf16.h>
#include <mma.h>
#include <math.h>
#include <string.h>

using namespace nvcuda;

// ---------------------------------------------------------------------------
// Shapes (fixed): x (16, 512, 32, 32) -> B=16, C=512, N=1024; heads=4, hd=128
// ---------------------------------------------------------------------------
#define B_   16
#define C_   512
#define N_   1024
#define HEADS 4
#define HD   128
#define GROUPS 32
#define GSIZE (C_ / GROUPS)
#define QKV_C (3 * C_)

// Scratch (device globals — allocation-free per harness rules)
__device__ __nv_bfloat16 g_y_bf [(size_t)B_ * C_ * N_];
__device__ __nv_bfloat16 g_qkv  [(size_t)B_ * QKV_C * N_];
__device__ __nv_bfloat16 g_o_bf [(size_t)B_ * C_ * N_];
__device__ __nv_bfloat16 g_wq_bf[(size_t)QKV_C * C_];
__device__ __nv_bfloat16 g_wp_bf[(size_t)C_ * C_];

// ---------------------------------------------------------------------------
// helpers
// ---------------------------------------------------------------------------
__device__ __forceinline__ unsigned bf2_bits(__nv_bfloat162 v)
{
    unsigned u; memcpy(&u, &v, 4); return u;
}
__device__ __forceinline__ void cp_async16(void* smem_dst, const void* gmem_src)
{
    unsigned s = (unsigned)__cvta_generic_to_shared(smem_dst);
    asm volatile("cp.async.cg.shared.global [%0], [%1], 16;\n" :: "r"(s), "l"(gmem_src));
}
__device__ __forceinline__ void cp_commit() { asm volatile("cp.async.commit_group;\n"); }
template<int N> __device__ __forceinline__ void cp_wait()
{ asm volatile("cp.async.wait_group %0;\n" :: "n"(N)); }

// ---------------------------------------------------------------------------
// fp32 -> bf16 conversion (weights)
// ---------------------------------------------------------------------------
__global__ void cvt_bf16_kernel(const float* __restrict__ a,
                                __nv_bfloat16* __restrict__ o, int n4)
{
    int i = blockIdx.x * blockDim.x + threadIdx.x;
    if (i < n4) {
        float4 v = *reinterpret_cast<const float4*>(a + (size_t)i * 4);
        *reinterpret_cast<__nv_bfloat162*>(o + (size_t)i * 4)     = __floats2bfloat162_rn(v.x, v.y);
        *reinterpret_cast<__nv_bfloat162*>(o + (size_t)i * 4 + 2) = __floats2bfloat162_rn(v.z, v.w);
    }
}

// ---------------------------------------------------------------------------
// GroupNorm -> bf16 output y[b][c][n]
// ---------------------------------------------------------------------------
__global__ void groupnorm_kernel(const float* __restrict__ x,
                                 const float* __restrict__ w,
                                 const float* __restrict__ bias,
                                 __nv_bfloat16* __restrict__ y)
{
    const int blk = blockIdx.x;
    const int g   = blk % GROUPS;
    const long base = (long)blk * (GSIZE * N_);
    const float* xp = x + base;
    __nv_bfloat16* yp = y + base;

    const int tid = threadIdx.x;
    float s = 0.f, s2 = 0.f;
    #pragma unroll 8
    for (int i = tid; i < GSIZE * N_; i += 256) {
        float v = xp[i];
        s += v; s2 += v * v;
    }
    __shared__ float rs[32], rs2[32];
    for (int off = 16; off > 0; off >>= 1) {
        s  += __shfl_down_sync(0xffffffffu, s,  off);
        s2 += __shfl_down_sync(0xffffffffu, s2, off);
    }
    if ((tid & 31) == 0) { rs[tid >> 5] = s; rs2[tid >> 5] = s2; }
    __syncthreads();
    if (tid < 32) {
        s  = (tid < 8) ? rs[tid]  : 0.f;
        s2 = (tid < 8) ? rs2[tid] : 0.f;
        for (int off = 4; off > 0; off >>= 1) {
            s  += __shfl_down_sync(0xffffffffu, s,  off);
            s2 += __shfl_down_sync(0xffffffffu, s2, off);
        }
        if (tid == 0) { rs[0] = s; rs2[0] = s2; }
    }
    __syncthreads();
    const float inv_n = 1.0f / (GSIZE * N_);
    const float mean  = rs[0] * inv_n;
    const float var   = rs2[0] * inv_n - mean * mean;
    const float rstd  = rsqrtf(var + 1e-5f);

    const int c0 = g * GSIZE;
    #pragma unroll 4
    for (int i = tid; i < GSIZE * N_; i += 256) {
        int ch = c0 + (i >> 10);
        yp[i] = __float2bfloat16((xp[i] - mean) * rstd * w[ch] + bias[ch]);
    }
}

// ---------------------------------------------------------------------------
// High-occupancy 2-stage cp.async BF16 wmma GEMM (3 CTAs/SM):
//   C[z] = A(MxK bf16) @ B[z](KxN bf16) + bias[m] (+ R[z] fp32)
// BM=128, BN=64, BK=64. 8 warps 4m x 2n; warp tile 32x32 (2x2 frags,
// 32 accumulator regs/thread) -> fits 84-reg cap for 3 CTAs/SM.
// ---------------------------------------------------------------------------
#define TBM 128
#define TBN 64
#define TBK 64
#define TLDA 72                                       // bf16 elems / A row
#define TLDB 72                                       // bf16 elems / B row
#define TSTG_BYTES (TBM * TLDA * 2 + TBK * TLDB * 2)  // 18432+9216 = 27648
#define TSM_BYTES  (2 * TSTG_BYTES)                   // 55296; epi St 34816 fits

template<int EPI, bool OUTB>   // EPI 1: +bias   2: +bias +residual
__global__ void __launch_bounds__(256, 3)
hgemm(const __nv_bfloat16* __restrict__ A, const __nv_bfloat16* __restrict__ B,
      void* __restrict__ Cv, int M, int K, int Nn,
      long sB, long sC, const float* __restrict__ bias,
      const float* __restrict__ R, long sR)
{
    extern __shared__ char smraw[];
    const int z = blockIdx.z;
    B += (long)z * sB;
    if (EPI == 2) R += (long)z * sR;

    const int tid = threadIdx.x;
    const int w   = tid >> 5;
    const int wm  = w >> 1;              // 0..3 (32-row slab)
    const int wn  = w & 1;               // 0..1 (32-col slab)
    const int m0  = blockIdx.y * TBM;
    const int n0  = blockIdx.x * TBN;

    auto issue_tile = [&](int k0, int st) {
        __nv_bfloat16* As = (__nv_bfloat16*)(smraw + st * TSTG_BYTES);
        __nv_bfloat16* Bs = As + TBM * TLDA;
        // A tile 128x64 bf16 = 1024 16B-chunks (8/row); 4 per thread
        #pragma unroll
        for (int it = 0; it < 4; it++) {
            int id = tid + it * 256;
            int r = id >> 3, c = (id & 7) * 8;
            cp_async16(As + r * TLDA + c, A + (long)(m0 + r) * K + k0 + c);
        }
        // B tile 64x64 bf16 = 512 16B-chunks (8/row); 2 per thread
        #pragma unroll
        for (int it = 0; it < 2; it++) {
            int id = tid + it * 256;
            int r = id >> 3, c = (id & 7) * 8;
            cp_async16(Bs + r * TLDB + c, B + (long)(k0 + r) * Nn + n0 + c);
        }
        cp_commit();
    };

    wmma::fragment<wmma::accumulator, 16, 16, 16, float> acc[2][2];
    #pragma unroll
    for (int i = 0; i < 2; i++)
        #pragma unroll
        for (int j = 0; j < 2; j++) wmma::fill_fragment(acc[i][j], 0.0f);

    const int tiles = K / TBK;
    issue_tile(0, 0);

    for (int t = 0; t < tiles; t++) {
        if (t + 1 < tiles) { issue_tile((t + 1) * TBK, (t + 1) & 1); cp_wait<1>(); }
        else               { cp_wait<0>(); }
        __syncthreads();

        const __nv_bfloat16* As = (const __nv_bfloat16*)(smraw + (t & 1) * TSTG_BYTES);
        const __nv_bfloat16* Bs = As + TBM * TLDA;
        #pragma unroll
        for (int ks = 0; ks < 4; ks++) {
            const int kk = ks * 16;
            wmma::fragment<wmma::matrix_a, 16, 16, 16, __nv_bfloat16,
                           wmma::row_major> af[2];
            wmma::fragment<wmma::matrix_b, 16, 16, 16, __nv_bfloat16,
                           wmma::row_major> bfr[2];
            #pragma unroll
            for (int i = 0; i < 2; i++)
                wmma::load_matrix_sync(af[i], As + (wm * 32 + i * 16) * TLDA + kk, TLDA);
            #pragma unroll
            for (int j = 0; j < 2; j++)
                wmma::load_matrix_sync(bfr[j], Bs + kk * TLDB + wn * 32 + j * 16, TLDB);
            #pragma unroll
            for (int i = 0; i < 2; i++)
                #pragma unroll
                for (int j = 0; j < 2; j++)
                    wmma::mma_sync(acc[i][j], af[i], bfr[j], acc[i][j]);
        }
        __syncthreads();
    }

    // epilogue: stage fp32 accumulators through smem, add bias (+residual)
    float* St = (float*)smraw;
    constexpr int ldS = TBN + 4;     // 68
    #pragma unroll
    for (int i = 0; i < 2; i++)
        #pragma unroll
        for (int j = 0; j < 2; j++)
            wmma::store_matrix_sync(St + (wm * 32 + i * 16) * ldS + wn * 32 + j * 16,
                                    acc[i][j], ldS, wmma::mem_row_major);
    __syncthreads();
    #pragma unroll
    for (int i = tid; i < TBM * (TBN / 4); i += 256) {
        int r = i >> 4, c = (i & 15) * 4;
        int gm = m0 + r, gn = n0 + c;
        float4 v = *reinterpret_cast<const float4*>(St + r * ldS + c);
        float bv = bias[gm];
        v.x += bv; v.y += bv; v.z += bv; v.w += bv;
        if (EPI == 2) {
            float4 rv = *reinterpret_cast<const float4*>(R + (long)gm * Nn + gn);
            v.x += rv.x; v.y += rv.y; v.z += rv.z; v.w += rv.w;
        }
        if (OUTB) {
            __nv_bfloat16* C = (__nv_bfloat16*)Cv + (long)z * sC;
            uint2 p;
            p.x = bf2_bits(__floats2bfloat162_rn(v.x, v.y));
            p.y = bf2_bits(__floats2bfloat162_rn(v.z, v.w));
            *reinterpret_cast<uint2*>(C + (long)gm * Nn + gn) = p;
        } else {
            float* C = (float*)Cv + (long)z * sC;
            *reinterpret_cast<float4*>(C + (long)gm * Nn + gn) = v;
        }
    }
}

// ---------------------------------------------------------------------------
// Fused flash attention (unchanged from R11; all-bf16 operands)
// ---------------------------------------------------------------------------
#define QT 128
#define KT 64
#define QLH 136
#define KLH 72
#define SL  68
#define SPL 72

#define OFB_Q  0
#define OFB_K  (OFB_Q + HD * QLH * 2)
#define OFB_V  (OFB_K + HD * KLH * 2)
#define OFB_SS (OFB_V + HD * KLH * 2)
#define OFB_SP (OFB_SS + QT * SL * 4)
#define OFB_M  (OFB_SP + QT * SPL * 2)
#define OFB_L  (OFB_M + QT * 4)
#define OFB_A  (OFB_L + QT * 4)
#define FLASH_SMEM_BYTES (OFB_A + QT * 4)

__device__ __forceinline__ void mma_bf16(float& c0, float& c1, float& c2, float& c3,
                                         unsigned a0, unsigned a1, unsigned a2, unsigned a3,
                                         unsigned b0, unsigned b1)
{
    asm volatile(
        "mma.sync.aligned.m16n8k16.row.col.f32.bf16.bf16.f32 "
        "{%0,%1,%2,%3}, {%4,%5,%6,%7}, {%8,%9}, {%0,%1,%2,%3};\n"
        : "+f"(c0), "+f"(c1), "+f"(c2), "+f"(c3)
        : "r"(a0), "r"(a1), "r"(a2), "r"(a3), "r"(b0), "r"(b1));
}

__global__ void __launch_bounds__(256)
flash_kernel(const __nv_bfloat16* __restrict__ qkv, __nv_bfloat16* __restrict__ o)
{
    extern __shared__ char smc[];
    __nv_bfloat16* Qs = (__nv_bfloat16*)(smc + OFB_Q);
    __nv_bfloat16* Ks = (__nv_bfloat16*)(smc + OFB_K);
    __nv_bfloat16* Vs = (__nv_bfloat16*)(smc + OFB_V);
    float*         Ss = (float*)(smc + OFB_SS);
    __nv_bfloat16* Sp = (__nv_bfloat16*)(smc + OFB_SP);
    float*         Ms = (float*)(smc + OFB_M);
    float*         Ls = (float*)(smc + OFB_L);
    float*         Al = (float*)(smc + OFB_A);

    const int tid  = threadIdx.x;
    const int w    = tid >> 5;
    const int lane = tid & 31;
    const int g    = lane >> 2;
    const int tig  = lane & 3;
    const int wm   = w >> 1;
    const int wn   = w & 1;

    const int q0 = blockIdx.x * QT;
    const int bh = blockIdx.y;
    const long base = ((long)(bh >> 2) * QKV_C + (long)(bh & 3) * HD) * N_;
    const __nv_bfloat16* Qg = qkv + base;
    const __nv_bfloat16* Kg = qkv + base + (long)C_ * N_;
    const __nv_bfloat16* Vg = qkv + base + 2L * (long)C_ * N_;
    __nv_bfloat16* Og = o + ((long)(bh >> 2) * C_ + (long)(bh & 3) * HD) * N_ + q0;

    const float scale = 0.08838834764831845f;

    #pragma unroll
    for (int i = tid; i < HD * 16; i += 256) {
        int r = i >> 4, c = (i & 15) * 8;
        *reinterpret_cast<uint4*>(Qs + r * QLH + c) =
            *reinterpret_cast<const uint4*>(Qg + (long)r * N_ + q0 + c);
    }
    if (tid < QT) { Ms[tid] = -1e30f; Ls[tid] = 0.f; }

    const int pr = tid >> 3, pc = (tid & 7) * 8;
    uint4 pk[4], pv[4];
    #pragma unroll
    for (int it = 0; it < 4; it++) {
        int r = pr + it * 32;
        pk[it] = *reinterpret_cast<const uint4*>(Kg + (long)r * N_ + pc);
        pv[it] = *reinterpret_cast<const uint4*>(Vg + (long)r * N_ + pc);
    }

    float oc[2][8][4];
    #pragma unroll
    for (int i = 0; i < 2; i++)
        #pragma unroll
        for (int j = 0; j < 8; j++)
            #pragma unroll
            for (int t = 0; t < 4; t++) oc[i][j][t] = 0.f;

    for (int kt = 0; kt < N_ / KT; kt++) {
        __syncthreads();

        #pragma unroll
        for (int it = 0; it < 4; it++) {
            int r = pr + it * 32;
            *reinterpret_cast<uint4*>(Ks + r * KLH + pc) = pk[it];
            *reinterpret_cast<uint4*>(Vs + r * KLH + pc) = pv[it];
        }
        if (kt + 1 < N_ / KT) {
            const int k0n = (kt + 1) * KT;
            #pragma unroll
            for (int it = 0; it < 4; it++) {
                int r = pr + it * 32;
                pk[it] = *reinterpret_cast<const uint4*>(Kg + (long)r * N_ + k0n + pc);
                pv[it] = *reinterpret_cast<const uint4*>(Vg + (long)r * N_ + k0n + pc);
            }
        }
        __syncthreads();

        {
            wmma::fragment<wmma::accumulator, 16, 16, 16, float> sacc[2][2];
            #pragma unroll
            for (int i = 0; i < 2; i++)
                #pragma unroll
                for (int j = 0; j < 2; j++) wmma::fill_fragment(sacc[i][j], 0.0f);

            #pragma unroll
            for (int kk = 0; kk < HD; kk += 16) {
                wmma::fragment<wmma::matrix_a, 16, 16, 16, __nv_bfloat16,
                               wmma::col_major> af[2];
                wmma::fragment<wmma::matrix_b, 16, 16, 16, __nv_bfloat16,
                               wmma::row_major> bf[2];
                #pragma unroll
                for (int i = 0; i < 2; i++)
                    wmma::load_matrix_sync(af[i], Qs + kk * QLH + wm * 32 + i * 16, QLH);
                #pragma unroll
                for (int j = 0; j < 2; j++)
                    wmma::load_matrix_sync(bf[j], Ks + kk * KLH + wn * 32 + j * 16, KLH);
                #pragma unroll
                for (int i = 0; i < 2; i++)
                    #pragma unroll
                    for (int j = 0; j < 2; j++)
                        wmma::mma_sync(sacc[i][j], af[i], bf[j], sacc[i][j]);
            }
            #pragma unroll
            for (int i = 0; i < 2; i++)
                #pragma unroll
                for (int j = 0; j < 2; j++) {
                    #pragma unroll
                    for (int t = 0; t < sacc[i][j].num_elements; t++)
                        sacc[i][j].x[t] *= scale;
                    wmma::store_matrix_sync(Ss + (wm * 32 + i * 16) * SL + wn * 32 + j * 16,
                                            sacc[i][j], SL, wmma::mem_row_major);
                }
        }
        __syncthreads();

        {
            const int r    = tid >> 1;
            const int half = tid & 1;
            float* row = Ss + r * SL + half * 32;
            __nv_bfloat16* prow = Sp + r * SPL + half * 32;
            float4 v[8];
            float mx = -1e30f;
            #pragma unroll
            for (int i = 0; i < 8; i++) {
                v[i] = *reinterpret_cast<const float4*>(row + i * 4);
                mx = fmaxf(mx, fmaxf(fmaxf(v[i].x, v[i].y), fmaxf(v[i].z, v[i].w)));
            }
            mx = fmaxf(mx, __shfl_xor_sync(0xffffffffu, mx, 1));
            const float mo = Ms[r];
            const float mn = fmaxf(mo, mx);
            const float alpha = __expf(mo - mn);
            float s = 0.f;
            #pragma unroll
            for (int i = 0; i < 8; i++) {
                v[i].x = __expf(v[i].x - mn); v[i].y = __expf(v[i].y - mn);
                v[i].z = __expf(v[i].z - mn); v[i].w = __expf(v[i].w - mn);
                s += v[i].x + v[i].y + v[i].z + v[i].w;
                uint2 p;
                p.x = bf2_bits(__floats2bfloat162_rn(v[i].x, v[i].y));
                p.y = bf2_bits(__floats2bfloat162_rn(v[i].z, v[i].w));
                *reinterpret_cast<uint2*>(prow + i * 4) = p;
            }
            s += __shfl_xor_sync(0xffffffffu, s, 1);
            if (half == 0) {
                Ms[r] = mn;
                Ls[r] = Ls[r] * alpha + s;
                Al[r] = alpha;
            }
        }
        __syncthreads();

        {
            const int qb = wn * 64;
            #pragma unroll
            for (int j = 0; j < 8; j++) {
                const float aE = Al[qb + j * 8 + 2 * tig];
                const float aO = Al[qb + j * 8 + 2 * tig + 1];
                #pragma unroll
                for (int i = 0; i < 2; i++) {
                    oc[i][j][0] *= aE; oc[i][j][1] *= aO;
                    oc[i][j][2] *= aE; oc[i][j][3] *= aO;
                }
            }
            #pragma unroll
            for (int kk = 0; kk < KT; kk += 16) {
                unsigned b0[8], b1[8];
                #pragma unroll
                for (int j = 0; j < 8; j++) {
                    const __nv_bfloat16* pr2 = Sp + (qb + j * 8 + g) * SPL + kk;
                    b0[j] = *reinterpret_cast<const unsigned*>(pr2 + 2 * tig);
                    b1[j] = *reinterpret_cast<const unsigned*>(pr2 + 8 + 2 * tig);
                }
                #pragma unroll
                for (int i = 0; i < 2; i++) {
                    const int dr = wm * 32 + i * 16;
                    const __nv_bfloat16* vr0 = Vs + (dr + g) * KLH + kk;
                    const __nv_bfloat16* vr1 = Vs + (dr + g + 8) * KLH + kk;
                    unsigned a0 = *reinterpret_cast<const unsigned*>(vr0 + 2 * tig);
                    unsigned a1 = *reinterpret_cast<const unsigned*>(vr1 + 2 * tig);
                    unsigned a2 = *reinterpret_cast<const unsigned*>(vr0 + 8 + 2 * tig);
                    unsigned a3 = *reinterpret_cast<const unsigned*>(vr1 + 8 + 2 * tig);
                    #pragma unroll
                    for (int j = 0; j < 8; j++)
                        mma_bf16(oc[i][j][0], oc[i][j][1], oc[i][j][2], oc[i][j][3],
                                 a0, a1, a2, a3, b0[j], b1[j]);
                }
            }
        }
    }

    {
        const int qb = wn * 64;
        #pragma unroll
        for (int j = 0; j < 8; j++) {
            const int qc = qb + j * 8 + 2 * tig;
            const float iE = 1.0f / Ls[qc];
            const float iO = 1.0f / Ls[qc + 1];
            #pragma unroll
            for (int i = 0; i < 2; i++) {
                const int dr = wm * 32 + i * 16;
                __nv_bfloat162 lo = __floats2bfloat162_rn(oc[i][j][0] * iE, oc[i][j][1] * iO);
                __nv_bfloat162 hi = __floats2bfloat162_rn(oc[i][j][2] * iE, oc[i][j][3] * iO);
                *reinterpret_cast<__nv_bfloat162*>(Og + (long)(dr + g) * N_ + qc) = lo;
                *reinterpret_cast<__nv_bfloat162*>(Og + (long)(dr + g + 8) * N_ + qc) = hi;
            }
        }
    }
}

// ---------------------------------------------------------------------------
// Launch
// ---------------------------------------------------------------------------
extern "C" void kernel_launch(void* const* d_in, const int* in_sizes, int n_in,
                              void* d_out, int out_size)
{
    const float* x      = (const float*)d_in[0];
    const float* norm_w = (const float*)d_in[1];
    const float* norm_b = (const float*)d_in[2];
    const float* qkv_w  = (const float*)d_in[3];
    const float* qkv_b  = (const float*)d_in[4];
    const float* proj_w = (const float*)d_in[5];
    const float* proj_b = (const float*)d_in[6];
    float* out          = (float*)d_out;

    __nv_bfloat16 *y, *o, *wq, *wp, *qkv;
    cudaGetSymbolAddress((void**)&y,   g_y_bf);
    cudaGetSymbolAddress((void**)&qkv, g_qkv);
    cudaGetSymbolAddress((void**)&o,   g_o_bf);
    cudaGetSymbolAddress((void**)&wq,  g_wq_bf);
    cudaGetSymbolAddress((void**)&wp,  g_wp_bf);

    // Idempotent attribute setup (not stream ops; safe under graph capture)
    cudaFuncSetAttribute(flash_kernel,
                         cudaFuncAttributeMaxDynamicSharedMemorySize,
                         FLASH_SMEM_BYTES);
    cudaFuncSetAttribute(hgemm<1, true>,
                         cudaFuncAttributeMaxDynamicSharedMemorySize, TSM_BYTES);
    cudaFuncSetAttribute(hgemm<2, false>,
                         cudaFuncAttributeMaxDynamicSharedMemorySize, TSM_BYTES);

    // 0) convert weights to bf16
    cvt_bf16_kernel<<<(QKV_C * C_ / 4 + 255) / 256, 256>>>(qkv_w, wq, QKV_C * C_ / 4);
    cvt_bf16_kernel<<<(C_ * C_ / 4 + 255) / 256, 256>>>(proj_w, wp, C_ * C_ / 4);

    // 1) GroupNorm -> bf16 y
    groupnorm_kernel<<<B_ * GROUPS, 256>>>(x, norm_w, norm_b, y);

    // 2) QKV (bf16 -> bf16): qkv[b] = wq @ y[b] + qkv_b
    {
        dim3 grid(N_ / TBN, QKV_C / TBM, B_);
        hgemm<1, true><<<grid, 256, TSM_BYTES>>>(
            wq, y, qkv, QKV_C, C_, N_,
            (long)C_ * N_, (long)QKV_C * N_, qkv_b, nullptr, 0);
    }

    // 3) Fused attention (all-bf16 operands) -> o
    {
        dim3 grid(N_ / QT, B_ * HEADS);
        flash_kernel<<<grid, 256, FLASH_SMEM_BYTES>>>(qkv, o);
    }

    // 4) out[b] = wp @ o[b] + proj_b + x[b]  (fp32 out)
    {
        dim3 grid(N_ / TBN, C_ / TBM, B_);
        hgemm<2, false><<<grid, 256, TSM_BYTES>>>(
            wp, o, out, C_, C_, N_,
            (long)C_ * N_, (long)C_ * N_, proj_b, x, (long)C_ * N_);
    }
}

// round 15
// speedup vs baseline: 1.0693x; 1.0693x over previous
#include <cuda_runtime.h>
#include <cuda_bf16.h>
#include <mma.h>
#include <math.h>
#include <string.h>

using namespace nvcuda;

// ---------------------------------------------------------------------------
// Shapes (fixed): x (16, 512, 32, 32) -> B=16, C=512, N=1024; heads=4, hd=128
// ---------------------------------------------------------------------------
#define B_   16
#define C_   512
#define N_   1024
#define HEADS 4
#define HD   128
#define GROUPS 32
#define GSIZE (C_ / GROUPS)
#define QKV_C (3 * C_)

// Scratch (device globals — allocation-free per harness rules)
__device__ __nv_bfloat16 g_y_bf [(size_t)B_ * C_ * N_];
__device__ __nv_bfloat16 g_qkv  [(size_t)B_ * QKV_C * N_];
__device__ __nv_bfloat16 g_o_bf [(size_t)B_ * C_ * N_];
__device__ __nv_bfloat16 g_wq_bf[(size_t)QKV_C * C_];
__device__ __nv_bfloat16 g_wp_bf[(size_t)C_ * C_];

// ---------------------------------------------------------------------------
// helpers
// ---------------------------------------------------------------------------
__device__ __forceinline__ unsigned bf2_bits(__nv_bfloat162 v)
{
    unsigned u; memcpy(&u, &v, 4); return u;
}
__device__ __forceinline__ void cp_async16(void* smem_dst, const void* gmem_src)
{
    unsigned s = (unsigned)__cvta_generic_to_shared(smem_dst);
    asm volatile("cp.async.cg.shared.global [%0], [%1], 16;\n" :: "r"(s), "l"(gmem_src));
}
__device__ __forceinline__ void cp_commit() { asm volatile("cp.async.commit_group;\n"); }
template<int N> __device__ __forceinline__ void cp_wait()
{ asm volatile("cp.async.wait_group %0;\n" :: "n"(N)); }

// ---------------------------------------------------------------------------
// fp32 -> bf16 conversion (weights)
// ---------------------------------------------------------------------------
__global__ void cvt_bf16_kernel(const float* __restrict__ a,
                                __nv_bfloat16* __restrict__ o, int n4)
{
    int i = blockIdx.x * blockDim.x + threadIdx.x;
    if (i < n4) {
        float4 v = *reinterpret_cast<const float4*>(a + (size_t)i * 4);
        *reinterpret_cast<__nv_bfloat162*>(o + (size_t)i * 4)     = __floats2bfloat162_rn(v.x, v.y);
        *reinterpret_cast<__nv_bfloat162*>(o + (size_t)i * 4 + 2) = __floats2bfloat162_rn(v.z, v.w);
    }
}

// ---------------------------------------------------------------------------
// GroupNorm -> bf16 output y[b][c][n]
// ---------------------------------------------------------------------------
__global__ void groupnorm_kernel(const float* __restrict__ x,
                                 const float* __restrict__ w,
                                 const float* __restrict__ bias,
                                 __nv_bfloat16* __restrict__ y)
{
    const int blk = blockIdx.x;
    const int g   = blk % GROUPS;
    const long base = (long)blk * (GSIZE * N_);
    const float* xp = x + base;
    __nv_bfloat16* yp = y + base;

    const int tid = threadIdx.x;
    float s = 0.f, s2 = 0.f;
    #pragma unroll 8
    for (int i = tid; i < GSIZE * N_; i += 256) {
        float v = xp[i];
        s += v; s2 += v * v;
    }
    __shared__ float rs[32], rs2[32];
    for (int off = 16; off > 0; off >>= 1) {
        s  += __shfl_down_sync(0xffffffffu, s,  off);
        s2 += __shfl_down_sync(0xffffffffu, s2, off);
    }
    if ((tid & 31) == 0) { rs[tid >> 5] = s; rs2[tid >> 5] = s2; }
    __syncthreads();
    if (tid < 32) {
        s  = (tid < 8) ? rs[tid]  : 0.f;
        s2 = (tid < 8) ? rs2[tid] : 0.f;
        for (int off = 4; off > 0; off >>= 1) {
            s  += __shfl_down_sync(0xffffffffu, s,  off);
            s2 += __shfl_down_sync(0xffffffffu, s2, off);
        }
        if (tid == 0) { rs[0] = s; rs2[0] = s2; }
    }
    __syncthreads();
    const float inv_n = 1.0f / (GSIZE * N_);
    const float mean  = rs[0] * inv_n;
    const float var   = rs2[0] * inv_n - mean * mean;
    const float rstd  = rsqrtf(var + 1e-5f);

    const int c0 = g * GSIZE;
    #pragma unroll 4
    for (int i = tid; i < GSIZE * N_; i += 256) {
        int ch = c0 + (i >> 10);
        yp[i] = __float2bfloat16((xp[i] - mean) * rstd * w[ch] + bias[ch]);
    }
}

// ---------------------------------------------------------------------------
// 2-stage cp.async BF16 wmma GEMM (R11-proven config):
//   C[z] = A(MxK bf16) @ B[z](KxN bf16) + bias[m] (+ R[z] fp32)
// BM=128, BN=128, BK=32. 8 warps 2m x 4n; warp tile 64x32.
// ---------------------------------------------------------------------------
#define TBM 128
#define TBN 128
#define TBK 32
#define TLDA 40
#define TLDB 136
#define TSTG_BYTES (TBM * TLDA * 2 + TBK * TLDB * 2)  // 18944
#define TSM_BYTES  (TBM * (TBN + 4) * 4)              // 67584 > 2*18944

template<int EPI, bool OUTB>   // EPI 1: +bias   2: +bias +residual
__global__ void __launch_bounds__(256, 2)
hgemm(const __nv_bfloat16* __restrict__ A, const __nv_bfloat16* __restrict__ B,
      void* __restrict__ Cv, int M, int K, int Nn,
      long sB, long sC, const float* __restrict__ bias,
      const float* __restrict__ R, long sR)
{
    extern __shared__ char smraw[];
    const int z = blockIdx.z;
    B += (long)z * sB;
    if (EPI == 2) R += (long)z * sR;

    const int tid = threadIdx.x;
    const int w   = tid >> 5;
    const int wm  = w >> 2;
    const int wn  = w & 3;
    const int m0  = blockIdx.y * TBM;
    const int n0  = blockIdx.x * TBN;

    auto issue_tile = [&](int k0, int st) {
        __nv_bfloat16* As = (__nv_bfloat16*)(smraw + st * TSTG_BYTES);
        __nv_bfloat16* Bs = As + TBM * TLDA;
        #pragma unroll
        for (int it = 0; it < 2; it++) {
            int id = tid + it * 256;
            int r = id >> 2, c = (id & 3) * 8;
            cp_async16(As + r * TLDA + c, A + (long)(m0 + r) * K + k0 + c);
        }
        #pragma unroll
        for (int it = 0; it < 2; it++) {
            int id = tid + it * 256;
            int r = id >> 4, c = (id & 15) * 8;
            cp_async16(Bs + r * TLDB + c, B + (long)(k0 + r) * Nn + n0 + c);
        }
        cp_commit();
    };

    wmma::fragment<wmma::accumulator, 16, 16, 16, float> acc[4][2];
    #pragma unroll
    for (int i = 0; i < 4; i++)
        #pragma unroll
        for (int j = 0; j < 2; j++) wmma::fill_fragment(acc[i][j], 0.0f);

    const int tiles = K / TBK;
    issue_tile(0, 0);

    for (int t = 0; t < tiles; t++) {
        if (t + 1 < tiles) { issue_tile((t + 1) * TBK, (t + 1) & 1); cp_wait<1>(); }
        else               { cp_wait<0>(); }
        __syncthreads();

        const __nv_bfloat16* As = (const __nv_bfloat16*)(smraw + (t & 1) * TSTG_BYTES);
        const __nv_bfloat16* Bs = As + TBM * TLDA;
        #pragma unroll
        for (int ks = 0; ks < 2; ks++) {
            const int kk = ks * 16;
            wmma::fragment<wmma::matrix_a, 16, 16, 16, __nv_bfloat16,
                           wmma::row_major> af[4];
            wmma::fragment<wmma::matrix_b, 16, 16, 16, __nv_bfloat16,
                           wmma::row_major> bfr[2];
            #pragma unroll
            for (int i = 0; i < 4; i++)
                wmma::load_matrix_sync(af[i], As + (wm * 64 + i * 16) * TLDA + kk, TLDA);
            #pragma unroll
            for (int j = 0; j < 2; j++)
                wmma::load_matrix_sync(bfr[j], Bs + kk * TLDB + wn * 32 + j * 16, TLDB);
            #pragma unroll
            for (int i = 0; i < 4; i++)
                #pragma unroll
                for (int j = 0; j < 2; j++)
                    wmma::mma_sync(acc[i][j], af[i], bfr[j], acc[i][j]);
        }
        __syncthreads();
    }

    float* St = (float*)smraw;
    constexpr int ldS = TBN + 4;
    #pragma unroll
    for (int i = 0; i < 4; i++)
        #pragma unroll
        for (int j = 0; j < 2; j++)
            wmma::store_matrix_sync(St + (wm * 64 + i * 16) * ldS + wn * 32 + j * 16,
                                    acc[i][j], ldS, wmma::mem_row_major);
    __syncthreads();
    #pragma unroll
    for (int i = tid; i < TBM * (TBN / 4); i += 256) {
        int r = i >> 5, c = (i & 31) * 4;
        int gm = m0 + r, gn = n0 + c;
        float4 v = *reinterpret_cast<const float4*>(St + r * ldS + c);
        float bv = bias[gm];
        v.x += bv; v.y += bv; v.z += bv; v.w += bv;
        if (EPI == 2) {
            float4 rv = *reinterpret_cast<const float4*>(R + (long)gm * Nn + gn);
            v.x += rv.x; v.y += rv.y; v.z += rv.z; v.w += rv.w;
        }
        if (OUTB) {
            __nv_bfloat16* C = (__nv_bfloat16*)Cv + (long)z * sC;
            uint2 p;
            p.x = bf2_bits(__floats2bfloat162_rn(v.x, v.y));
            p.y = bf2_bits(__floats2bfloat162_rn(v.z, v.w));
            *reinterpret_cast<uint2*>(C + (long)gm * Nn + gn) = p;
        } else {
            float* C = (float*)Cv + (long)z * sC;
            *reinterpret_cast<float4*>(C + (long)gm * Nn + gn) = v;
        }
    }
}

// ---------------------------------------------------------------------------
// Fused flash attention, 2 CTAs/SM version:
//   - P (bf16) written over the Ss (fp32) region  -> smem 105.5 KB
//   - K/V loads via cp.async; K tile for kt+1 issued during softmax/PV
//   - no register prefetch (peer CTA hides latency); regs capped at 128
// ---------------------------------------------------------------------------
#define QT 128
#define KT 64
#define QLH 136                 // Q smem row (bf16 elems)
#define KLH 72                  // K/V smem row (bf16 elems)
#define SL  68                  // Ss fp32 row (bf16 row stride = 136)

#define OFB_Q  0
#define OFB_K  (OFB_Q + HD * QLH * 2)       // 34816
#define OFB_V  (OFB_K + HD * KLH * 2)       // 53248
#define OFB_SS (OFB_V + HD * KLH * 2)       // 71680
#define OFB_M  (OFB_SS + QT * SL * 4)       // 106496
#define OFB_L  (OFB_M + QT * 4)
#define OFB_A  (OFB_L + QT * 4)
#define FLASH_SMEM_BYTES (OFB_A + QT * 4)   // 108032 (105.5 KB) -> 2 CTAs/SM

__device__ __forceinline__ void mma_bf16(float& c0, float& c1, float& c2, float& c3,
                                         unsigned a0, unsigned a1, unsigned a2, unsigned a3,
                                         unsigned b0, unsigned b1)
{
    asm volatile(
        "mma.sync.aligned.m16n8k16.row.col.f32.bf16.bf16.f32 "
        "{%0,%1,%2,%3}, {%4,%5,%6,%7}, {%8,%9}, {%0,%1,%2,%3};\n"
        : "+f"(c0), "+f"(c1), "+f"(c2), "+f"(c3)
        : "r"(a0), "r"(a1), "r"(a2), "r"(a3), "r"(b0), "r"(b1));
}

__global__ void __launch_bounds__(256, 2)
flash_kernel(const __nv_bfloat16* __restrict__ qkv, __nv_bfloat16* __restrict__ o)
{
    extern __shared__ char smc[];
    __nv_bfloat16* Qs = (__nv_bfloat16*)(smc + OFB_Q);
    __nv_bfloat16* Ks = (__nv_bfloat16*)(smc + OFB_K);
    __nv_bfloat16* Vs = (__nv_bfloat16*)(smc + OFB_V);
    float*         Ss = (float*)(smc + OFB_SS);
    __nv_bfloat16* SpA = (__nv_bfloat16*)(smc + OFB_SS);  // P aliases Ss
    float*         Ms = (float*)(smc + OFB_M);
    float*         Ls = (float*)(smc + OFB_L);
    float*         Al = (float*)(smc + OFB_A);

    const int tid  = threadIdx.x;
    const int w    = tid >> 5;
    const int lane = tid & 31;
    const int g    = lane >> 2;
    const int tig  = lane & 3;
    const int wm   = w >> 1;
    const int wn   = w & 1;

    const int q0 = blockIdx.x * QT;
    const int bh = blockIdx.y;
    const long base = ((long)(bh >> 2) * QKV_C + (long)(bh & 3) * HD) * N_;
    const __nv_bfloat16* Qg = qkv + base;
    const __nv_bfloat16* Kg = qkv + base + (long)C_ * N_;
    const __nv_bfloat16* Vg = qkv + base + 2L * (long)C_ * N_;
    __nv_bfloat16* Og = o + ((long)(bh >> 2) * C_ + (long)(bh & 3) * HD) * N_ + q0;

    const float scale = 0.08838834764831845f;

    // per-thread K/V copy coords: 4 chunks of 8 bf16 per tile each
    const int pr = tid >> 3, pc = (tid & 7) * 8;

    auto issue_K = [&](int k0) {
        #pragma unroll
        for (int it = 0; it < 4; it++) {
            int r = pr + it * 32;
            cp_async16(Ks + r * KLH + pc, Kg + (long)r * N_ + k0 + pc);
        }
        cp_commit();
    };
    auto issue_V = [&](int k0) {
        #pragma unroll
        for (int it = 0; it < 4; it++) {
            int r = pr + it * 32;
            cp_async16(Vs + r * KLH + pc, Vg + (long)r * N_ + k0 + pc);
        }
        cp_commit();
    };

    // Q tile [128 d][128 q] bf16
    #pragma unroll
    for (int i = tid; i < HD * 16; i += 256) {
        int r = i >> 4, c = (i & 15) * 8;
        *reinterpret_cast<uint4*>(Qs + r * QLH + c) =
            *reinterpret_cast<const uint4*>(Qg + (long)r * N_ + q0 + c);
    }
    if (tid < QT) { Ms[tid] = -1e30f; Ls[tid] = 0.f; }
    issue_K(0);
    issue_V(0);

    float oc[2][8][4];
    #pragma unroll
    for (int i = 0; i < 2; i++)
        #pragma unroll
        for (int j = 0; j < 8; j++)
            #pragma unroll
            for (int t = 0; t < 4; t++) oc[i][j][t] = 0.f;

    for (int kt = 0; kt < N_ / KT; kt++) {
        cp_wait<0>();          // K(kt) and V(kt) in smem
        __syncthreads();

        // S = Q^T K  (bf16 wmma m16n16k16, fp32 accum)
        {
            wmma::fragment<wmma::accumulator, 16, 16, 16, float> sacc[2][2];
            #pragma unroll
            for (int i = 0; i < 2; i++)
                #pragma unroll
                for (int j = 0; j < 2; j++) wmma::fill_fragment(sacc[i][j], 0.0f);

            #pragma unroll
            for (int kk = 0; kk < HD; kk += 16) {
                wmma::fragment<wmma::matrix_a, 16, 16, 16, __nv_bfloat16,
                               wmma::col_major> af[2];
                wmma::fragment<wmma::matrix_b, 16, 16, 16, __nv_bfloat16,
                               wmma::row_major> bf[2];
                #pragma unroll
                for (int i = 0; i < 2; i++)
                    wmma::load_matrix_sync(af[i], Qs + kk * QLH + wm * 32 + i * 16, QLH);
                #pragma unroll
                for (int j = 0; j < 2; j++)
                    wmma::load_matrix_sync(bf[j], Ks + kk * KLH + wn * 32 + j * 16, KLH);
                #pragma unroll
                for (int i = 0; i < 2; i++)
                    #pragma unroll
                    for (int j = 0; j < 2; j++)
                        wmma::mma_sync(sacc[i][j], af[i], bf[j], sacc[i][j]);
            }
            #pragma unroll
            for (int i = 0; i < 2; i++)
                #pragma unroll
                for (int j = 0; j < 2; j++) {
                    #pragma unroll
                    for (int t = 0; t < sacc[i][j].num_elements; t++)
                        sacc[i][j].x[t] *= scale;
                    wmma::store_matrix_sync(Ss + (wm * 32 + i * 16) * SL + wn * 32 + j * 16,
                                            sacc[i][j], SL, wmma::mem_row_major);
                }
        }
        __syncthreads();

        // Ks now free: prefetch next K tile during softmax + PV
        if (kt + 1 < N_ / KT) issue_K((kt + 1) * KT);

        // online softmax; P (bf16) written over the same Ss rows.
        // Thread pair (2r, 2r+1) shares a warp; all reads of the fp32 row
        // complete (in-registers) before any bf16 overwrite.
        {
            const int r    = tid >> 1;
            const int half = tid & 1;
            float* row = Ss + r * SL + half * 32;
            __nv_bfloat16* prow = SpA + r * (SL * 2) + half * 32;
            float4 v[8];
            float mx = -1e30f;
            #pragma unroll
            for (int i = 0; i < 8; i++) {
                v[i] = *reinterpret_cast<const float4*>(row + i * 4);
                mx = fmaxf(mx, fmaxf(fmaxf(v[i].x, v[i].y), fmaxf(v[i].z, v[i].w)));
            }
            mx = fmaxf(mx, __shfl_xor_sync(0xffffffffu, mx, 1));
            const float mo = Ms[r];
            const float mn = fmaxf(mo, mx);
            const float alpha = __expf(mo - mn);
            float s = 0.f;
            #pragma unroll
            for (int i = 0; i < 8; i++) {
                v[i].x = __expf(v[i].x - mn); v[i].y = __expf(v[i].y - mn);
                v[i].z = __expf(v[i].z - mn); v[i].w = __expf(v[i].w - mn);
                s += v[i].x + v[i].y + v[i].z + v[i].w;
                uint2 p;
                p.x = bf2_bits(__floats2bfloat162_rn(v[i].x, v[i].y));
                p.y = bf2_bits(__floats2bfloat162_rn(v[i].z, v[i].w));
                *reinterpret_cast<uint2*>(prow + i * 4) = p;
            }
            s += __shfl_xor_sync(0xffffffffu, s, 1);
            if (half == 0) {
                Ms[r] = mn;
                Ls[r] = Ls[r] * alpha + s;
                Al[r] = alpha;
            }
        }
        __syncthreads();

        // rescale O by alpha, then O^T += V @ P^T  (bf16 m16n8k16)
        {
            const int qb = wn * 64;
            #pragma unroll
            for (int j = 0; j < 8; j++) {
                const float aE = Al[qb + j * 8 + 2 * tig];
                const float aO = Al[qb + j * 8 + 2 * tig + 1];
                #pragma unroll
                for (int i = 0; i < 2; i++) {
                    oc[i][j][0] *= aE; oc[i][j][1] *= aO;
                    oc[i][j][2] *= aE; oc[i][j][3] *= aO;
                }
            }
            #pragma unroll
            for (int kk = 0; kk < KT; kk += 16) {
                unsigned b0[8], b1[8];
                #pragma unroll
                for (int j = 0; j < 8; j++) {
                    const __nv_bfloat16* pr2 = SpA + (qb + j * 8 + g) * (SL * 2) + kk;
                    b0[j] = *reinterpret_cast<const unsigned*>(pr2 + 2 * tig);
                    b1[j] = *reinterpret_cast<const unsigned*>(pr2 + 8 + 2 * tig);
                }
                #pragma unroll
                for (int i = 0; i < 2; i++) {
                    const int dr = wm * 32 + i * 16;
                    const __nv_bfloat16* vr0 = Vs + (dr + g) * KLH + kk;
                    const __nv_bfloat16* vr1 = Vs + (dr + g + 8) * KLH + kk;
                    unsigned a0 = *reinterpret_cast<const unsigned*>(vr0 + 2 * tig);
                    unsigned a1 = *reinterpret_cast<const unsigned*>(vr1 + 2 * tig);
                    unsigned a2 = *reinterpret_cast<const unsigned*>(vr0 + 8 + 2 * tig);
                    unsigned a3 = *reinterpret_cast<const unsigned*>(vr1 + 8 + 2 * tig);
                    #pragma unroll
                    for (int j = 0; j < 8; j++)
                        mma_bf16(oc[i][j][0], oc[i][j][1], oc[i][j][2], oc[i][j][3],
                                 a0, a1, a2, a3, b0[j], b1[j]);
                }
            }
        }
        __syncthreads();       // PV done reading Vs; safe to refill V

        if (kt + 1 < N_ / KT) issue_V((kt + 1) * KT);
    }

    // final: /l, store O^T as bf16 pairs
    {
        const int qb = wn * 64;
        #pragma unroll
        for (int j = 0; j < 8; j++) {
            const int qc = qb + j * 8 + 2 * tig;
            const float iE = 1.0f / Ls[qc];
            const float iO = 1.0f / Ls[qc + 1];
            #pragma unroll
            for (int i = 0; i < 2; i++) {
                const int dr = wm * 32 + i * 16;
                __nv_bfloat162 lo = __floats2bfloat162_rn(oc[i][j][0] * iE, oc[i][j][1] * iO);
                __nv_bfloat162 hi = __floats2bfloat162_rn(oc[i][j][2] * iE, oc[i][j][3] * iO);
                *reinterpret_cast<__nv_bfloat162*>(Og + (long)(dr + g) * N_ + qc) = lo;
                *reinterpret_cast<__nv_bfloat162*>(Og + (long)(dr + g + 8) * N_ + qc) = hi;
            }
        }
    }
}

// ---------------------------------------------------------------------------
// Launch
// ---------------------------------------------------------------------------
extern "C" void kernel_launch(void* const* d_in, const int* in_sizes, int n_in,
                              void* d_out, int out_size)
{
    const float* x      = (const float*)d_in[0];
    const float* norm_w = (const float*)d_in[1];
    const float* norm_b = (const float*)d_in[2];
    const float* qkv_w  = (const float*)d_in[3];
    const float* qkv_b  = (const float*)d_in[4];
    const float* proj_w = (const float*)d_in[5];
    const float* proj_b = (const float*)d_in[6];
    float* out          = (float*)d_out;

    __nv_bfloat16 *y, *o, *wq, *wp, *qkv;
    cudaGetSymbolAddress((void**)&y,   g_y_bf);
    cudaGetSymbolAddress((void**)&qkv, g_qkv);
    cudaGetSymbolAddress((void**)&o,   g_o_bf);
    cudaGetSymbolAddress((void**)&wq,  g_wq_bf);
    cudaGetSymbolAddress((void**)&wp,  g_wp_bf);

    // Idempotent attribute setup (not stream ops; safe under graph capture)
    cudaFuncSetAttribute(flash_kernel,
                         cudaFuncAttributeMaxDynamicSharedMemorySize,
                         FLASH_SMEM_BYTES);
    cudaFuncSetAttribute(hgemm<1, true>,
                         cudaFuncAttributeMaxDynamicSharedMemorySize, TSM_BYTES);
    cudaFuncSetAttribute(hgemm<2, false>,
                         cudaFuncAttributeMaxDynamicSharedMemorySize, TSM_BYTES);

    // 0) convert weights to bf16
    cvt_bf16_kernel<<<(QKV_C * C_ / 4 + 255) / 256, 256>>>(qkv_w, wq, QKV_C * C_ / 4);
    cvt_bf16_kernel<<<(C_ * C_ / 4 + 255) / 256, 256>>>(proj_w, wp, C_ * C_ / 4);

    // 1) GroupNorm -> bf16 y
    groupnorm_kernel<<<B_ * GROUPS, 256>>>(x, norm_w, norm_b, y);

    // 2) QKV (bf16 -> bf16): qkv[b] = wq @ y[b] + qkv_b
    {
        dim3 grid(N_ / TBN, QKV_C / TBM, B_);
        hgemm<1, true><<<grid, 256, TSM_BYTES>>>(
            wq, y, qkv, QKV_C, C_, N_,
            (long)C_ * N_, (long)QKV_C * N_, qkv_b, nullptr, 0);
    }

    // 3) Fused attention (2 CTAs/SM) -> o
    {
        dim3 grid(N_ / QT, B_ * HEADS);
        flash_kernel<<<grid, 256, FLASH_SMEM_BYTES>>>(qkv, o);
    }

    // 4) out[b] = wp @ o[b] + proj_b + x[b]  (fp32 out)
    {
        dim3 grid(N_ / TBN, C_ / TBM, B_);
        hgemm<2, false><<<grid, 256, TSM_BYTES>>>(
            wp, o, out, C_, C_, N_,
            (long)C_ * N_, (long)C_ * N_, proj_b, x, (long)C_ * N_);
    }
}

// round 16
// speedup vs baseline: 1.0890x; 1.0184x over previous
#include <cuda_runtime.h>
#include <cuda_bf16.h>
#include <mma.h>
#include <math.h>
#include <string.h>

using namespace nvcuda;

// ---------------------------------------------------------------------------
// Shapes (fixed): x (16, 512, 32, 32) -> B=16, C=512, N=1024; heads=4, hd=128
// ---------------------------------------------------------------------------
#define B_   16
#define C_   512
#define N_   1024
#define HEADS 4
#define HD   128
#define GROUPS 32
#define GSIZE (C_ / GROUPS)
#define QKV_C (3 * C_)

// Scratch (device globals — allocation-free per harness rules)
__device__ __nv_bfloat16 g_y_bf [(size_t)B_ * C_ * N_];
__device__ __nv_bfloat16 g_qkv  [(size_t)B_ * QKV_C * N_];
__device__ __nv_bfloat16 g_o_bf [(size_t)B_ * C_ * N_];
__device__ __nv_bfloat16 g_wq_bf[(size_t)QKV_C * C_];
__device__ __nv_bfloat16 g_wp_bf[(size_t)C_ * C_];

// ---------------------------------------------------------------------------
// helpers
// ---------------------------------------------------------------------------
__device__ __forceinline__ unsigned bf2_bits(__nv_bfloat162 v)
{
    unsigned u; memcpy(&u, &v, 4); return u;
}
__device__ __forceinline__ void cp_async16(void* smem_dst, const void* gmem_src)
{
    unsigned s = (unsigned)__cvta_generic_to_shared(smem_dst);
    asm volatile("cp.async.cg.shared.global [%0], [%1], 16;\n" :: "r"(s), "l"(gmem_src));
}
__device__ __forceinline__ void cp_commit() { asm volatile("cp.async.commit_group;\n"); }
template<int N> __device__ __forceinline__ void cp_wait()
{ asm volatile("cp.async.wait_group %0;\n" :: "n"(N)); }

// ---------------------------------------------------------------------------
// Fused prep: GroupNorm (blocks 0..511) + weight bf16 conversion
// (blocks 512..1279 -> qkv_w, 1280..1535 -> proj_w). One launch.
// ---------------------------------------------------------------------------
__global__ void prep_kernel(const float* __restrict__ x,
                            const float* __restrict__ w,
                            const float* __restrict__ bias,
                            __nv_bfloat16* __restrict__ y,
                            const float* __restrict__ qkv_w,
                            __nv_bfloat16* __restrict__ wq,
                            const float* __restrict__ proj_w,
                            __nv_bfloat16* __restrict__ wp)
{
    const int blk = blockIdx.x;
    if (blk >= B_ * GROUPS) {
        // weight conversion branch: one f4 per thread
        const int cb = blk - B_ * GROUPS;       // 0..1023
        const float* src;
        __nv_bfloat16* dst;
        int i;
        if (cb < 768) { src = qkv_w;  dst = wq; i = cb * 256 + threadIdx.x; }
        else          { src = proj_w; dst = wp; i = (cb - 768) * 256 + threadIdx.x; }
        float4 v = *reinterpret_cast<const float4*>(src + (size_t)i * 4);
        *reinterpret_cast<__nv_bfloat162*>(dst + (size_t)i * 4)     = __floats2bfloat162_rn(v.x, v.y);
        *reinterpret_cast<__nv_bfloat162*>(dst + (size_t)i * 4 + 2) = __floats2bfloat162_rn(v.z, v.w);
        return;
    }

    // GroupNorm branch
    const int g   = blk % GROUPS;
    const long base = (long)blk * (GSIZE * N_);
    const float* xp = x + base;
    __nv_bfloat16* yp = y + base;

    const int tid = threadIdx.x;
    float s = 0.f, s2 = 0.f;
    #pragma unroll 8
    for (int i = tid; i < GSIZE * N_; i += 256) {
        float v = xp[i];
        s += v; s2 += v * v;
    }
    __shared__ float rs[32], rs2[32];
    for (int off = 16; off > 0; off >>= 1) {
        s  += __shfl_down_sync(0xffffffffu, s,  off);
        s2 += __shfl_down_sync(0xffffffffu, s2, off);
    }
    if ((tid & 31) == 0) { rs[tid >> 5] = s; rs2[tid >> 5] = s2; }
    __syncthreads();
    if (tid < 32) {
        s  = (tid < 8) ? rs[tid]  : 0.f;
        s2 = (tid < 8) ? rs2[tid] : 0.f;
        for (int off = 4; off > 0; off >>= 1) {
            s  += __shfl_down_sync(0xffffffffu, s,  off);
            s2 += __shfl_down_sync(0xffffffffu, s2, off);
        }
        if (tid == 0) { rs[0] = s; rs2[0] = s2; }
    }
    __syncthreads();
    const float inv_n = 1.0f / (GSIZE * N_);
    const float mean  = rs[0] * inv_n;
    const float var   = rs2[0] * inv_n - mean * mean;
    const float rstd  = rsqrtf(var + 1e-5f);

    const int c0 = g * GSIZE;
    #pragma unroll 4
    for (int i = tid; i < GSIZE * N_; i += 256) {
        int ch = c0 + (i >> 10);
        yp[i] = __float2bfloat16((xp[i] - mean) * rstd * w[ch] + bias[ch]);
    }
}

// ---------------------------------------------------------------------------
// 2-stage cp.async BF16 wmma GEMM (R11-proven config):
//   C[z] = A(MxK bf16) @ B[z](KxN bf16) + bias[m] (+ R[z] fp32)
// BM=128, BN=128, BK=32. 8 warps 2m x 4n; warp tile 64x32.
// ---------------------------------------------------------------------------
#define TBM 128
#define TBN 128
#define TBK 32
#define TLDA 40
#define TLDB 136
#define TSTG_BYTES (TBM * TLDA * 2 + TBK * TLDB * 2)  // 18944
#define TSM_BYTES  (TBM * (TBN + 4) * 4)              // 67584 > 2*18944

template<int EPI, bool OUTB>   // EPI 1: +bias   2: +bias +residual
__global__ void __launch_bounds__(256, 2)
hgemm(const __nv_bfloat16* __restrict__ A, const __nv_bfloat16* __restrict__ B,
      void* __restrict__ Cv, int M, int K, int Nn,
      long sB, long sC, const float* __restrict__ bias,
      const float* __restrict__ R, long sR)
{
    extern __shared__ char smraw[];
    const int z = blockIdx.z;
    B += (long)z * sB;
    if (EPI == 2) R += (long)z * sR;

    const int tid = threadIdx.x;
    const int w   = tid >> 5;
    const int wm  = w >> 2;
    const int wn  = w & 3;
    const int m0  = blockIdx.y * TBM;
    const int n0  = blockIdx.x * TBN;

    auto issue_tile = [&](int k0, int st) {
        __nv_bfloat16* As = (__nv_bfloat16*)(smraw + st * TSTG_BYTES);
        __nv_bfloat16* Bs = As + TBM * TLDA;
        #pragma unroll
        for (int it = 0; it < 2; it++) {
            int id = tid + it * 256;
            int r = id >> 2, c = (id & 3) * 8;
            cp_async16(As + r * TLDA + c, A + (long)(m0 + r) * K + k0 + c);
        }
        #pragma unroll
        for (int it = 0; it < 2; it++) {
            int id = tid + it * 256;
            int r = id >> 4, c = (id & 15) * 8;
            cp_async16(Bs + r * TLDB + c, B + (long)(k0 + r) * Nn + n0 + c);
        }
        cp_commit();
    };

    wmma::fragment<wmma::accumulator, 16, 16, 16, float> acc[4][2];
    #pragma unroll
    for (int i = 0; i < 4; i++)
        #pragma unroll
        for (int j = 0; j < 2; j++) wmma::fill_fragment(acc[i][j], 0.0f);

    const int tiles = K / TBK;
    issue_tile(0, 0);

    for (int t = 0; t < tiles; t++) {
        if (t + 1 < tiles) { issue_tile((t + 1) * TBK, (t + 1) & 1); cp_wait<1>(); }
        else               { cp_wait<0>(); }
        __syncthreads();

        const __nv_bfloat16* As = (const __nv_bfloat16*)(smraw + (t & 1) * TSTG_BYTES);
        const __nv_bfloat16* Bs = As + TBM * TLDA;
        #pragma unroll
        for (int ks = 0; ks < 2; ks++) {
            const int kk = ks * 16;
            wmma::fragment<wmma::matrix_a, 16, 16, 16, __nv_bfloat16,
                           wmma::row_major> af[4];
            wmma::fragment<wmma::matrix_b, 16, 16, 16, __nv_bfloat16,
                           wmma::row_major> bfr[2];
            #pragma unroll
            for (int i = 0; i < 4; i++)
                wmma::load_matrix_sync(af[i], As + (wm * 64 + i * 16) * TLDA + kk, TLDA);
            #pragma unroll
            for (int j = 0; j < 2; j++)
                wmma::load_matrix_sync(bfr[j], Bs + kk * TLDB + wn * 32 + j * 16, TLDB);
            #pragma unroll
            for (int i = 0; i < 4; i++)
                #pragma unroll
                for (int j = 0; j < 2; j++)
                    wmma::mma_sync(acc[i][j], af[i], bfr[j], acc[i][j]);
        }
        __syncthreads();
    }

    float* St = (float*)smraw;
    constexpr int ldS = TBN + 4;
    #pragma unroll
    for (int i = 0; i < 4; i++)
        #pragma unroll
        for (int j = 0; j < 2; j++)
            wmma::store_matrix_sync(St + (wm * 64 + i * 16) * ldS + wn * 32 + j * 16,
                                    acc[i][j], ldS, wmma::mem_row_major);
    __syncthreads();
    #pragma unroll
    for (int i = tid; i < TBM * (TBN / 4); i += 256) {
        int r = i >> 5, c = (i & 31) * 4;
        int gm = m0 + r, gn = n0 + c;
        float4 v = *reinterpret_cast<const float4*>(St + r * ldS + c);
        float bv = bias[gm];
        v.x += bv; v.y += bv; v.z += bv; v.w += bv;
        if (EPI == 2) {
            float4 rv = *reinterpret_cast<const float4*>(R + (long)gm * Nn + gn);
            v.x += rv.x; v.y += rv.y; v.z += rv.z; v.w += rv.w;
        }
        if (OUTB) {
            __nv_bfloat16* C = (__nv_bfloat16*)Cv + (long)z * sC;
            uint2 p;
            p.x = bf2_bits(__floats2bfloat162_rn(v.x, v.y));
            p.y = bf2_bits(__floats2bfloat162_rn(v.z, v.w));
            *reinterpret_cast<uint2*>(C + (long)gm * Nn + gn) = p;
        } else {
            float* C = (float*)Cv + (long)z * sC;
            *reinterpret_cast<float4*>(C + (long)gm * Nn + gn) = v;
        }
    }
}

// ---------------------------------------------------------------------------
// Fused flash attention, 2 CTAs/SM, split K/V cp.async waits:
//   - S-GEMM waits only on K (V load overlaps S-GEMM)
//   - V wait deferred to just before PV
//   - P (bf16) aliases the Ss (fp32) region -> smem 105.5 KB
// ---------------------------------------------------------------------------
#define QT 128
#define KT 64
#define QLH 136                 // Q smem row (bf16 elems)
#define KLH 72                  // K/V smem row (bf16 elems)
#define SL  68                  // Ss fp32 row (bf16 row stride = 136)

#define OFB_Q  0
#define OFB_K  (OFB_Q + HD * QLH * 2)       // 34816
#define OFB_V  (OFB_K + HD * KLH * 2)       // 53248
#define OFB_SS (OFB_V + HD * KLH * 2)       // 71680
#define OFB_M  (OFB_SS + QT * SL * 4)       // 106496
#define OFB_L  (OFB_M + QT * 4)
#define OFB_A  (OFB_L + QT * 4)
#define FLASH_SMEM_BYTES (OFB_A + QT * 4)   // 108032 (105.5 KB) -> 2 CTAs/SM

__device__ __forceinline__ void mma_bf16(float& c0, float& c1, float& c2, float& c3,
                                         unsigned a0, unsigned a1, unsigned a2, unsigned a3,
                                         unsigned b0, unsigned b1)
{
    asm volatile(
        "mma.sync.aligned.m16n8k16.row.col.f32.bf16.bf16.f32 "
        "{%0,%1,%2,%3}, {%4,%5,%6,%7}, {%8,%9}, {%0,%1,%2,%3};\n"
        : "+f"(c0), "+f"(c1), "+f"(c2), "+f"(c3)
        : "r"(a0), "r"(a1), "r"(a2), "r"(a3), "r"(b0), "r"(b1));
}

__global__ void __launch_bounds__(256, 2)
flash_kernel(const __nv_bfloat16* __restrict__ qkv, __nv_bfloat16* __restrict__ o)
{
    extern __shared__ char smc[];
    __nv_bfloat16* Qs = (__nv_bfloat16*)(smc + OFB_Q);
    __nv_bfloat16* Ks = (__nv_bfloat16*)(smc + OFB_K);
    __nv_bfloat16* Vs = (__nv_bfloat16*)(smc + OFB_V);
    float*         Ss = (float*)(smc + OFB_SS);
    __nv_bfloat16* SpA = (__nv_bfloat16*)(smc + OFB_SS);  // P aliases Ss
    float*         Ms = (float*)(smc + OFB_M);
    float*         Ls = (float*)(smc + OFB_L);
    float*         Al = (float*)(smc + OFB_A);

    const int tid  = threadIdx.x;
    const int w    = tid >> 5;
    const int lane = tid & 31;
    const int g    = lane >> 2;
    const int tig  = lane & 3;
    const int wm   = w >> 1;
    const int wn   = w & 1;

    const int q0 = blockIdx.x * QT;
    const int bh = blockIdx.y;
    const long base = ((long)(bh >> 2) * QKV_C + (long)(bh & 3) * HD) * N_;
    const __nv_bfloat16* Qg = qkv + base;
    const __nv_bfloat16* Kg = qkv + base + (long)C_ * N_;
    const __nv_bfloat16* Vg = qkv + base + 2L * (long)C_ * N_;
    __nv_bfloat16* Og = o + ((long)(bh >> 2) * C_ + (long)(bh & 3) * HD) * N_ + q0;

    const float scale = 0.08838834764831845f;

    // per-thread K/V copy coords: 4 chunks of 8 bf16 per tile each
    const int pr = tid >> 3, pc = (tid & 7) * 8;

    auto issue_K = [&](int k0) {
        #pragma unroll
        for (int it = 0; it < 4; it++) {
            int r = pr + it * 32;
            cp_async16(Ks + r * KLH + pc, Kg + (long)r * N_ + k0 + pc);
        }
        cp_commit();
    };
    auto issue_V = [&](int k0) {
        #pragma unroll
        for (int it = 0; it < 4; it++) {
            int r = pr + it * 32;
            cp_async16(Vs + r * KLH + pc, Vg + (long)r * N_ + k0 + pc);
        }
        cp_commit();
    };

    // Q tile [128 d][128 q] bf16
    #pragma unroll
    for (int i = tid; i < HD * 16; i += 256) {
        int r = i >> 4, c = (i & 15) * 8;
        *reinterpret_cast<uint4*>(Qs + r * QLH + c) =
            *reinterpret_cast<const uint4*>(Qg + (long)r * N_ + q0 + c);
    }
    if (tid < QT) { Ms[tid] = -1e30f; Ls[tid] = 0.f; }
    issue_K(0);
    issue_V(0);

    float oc[2][8][4];
    #pragma unroll
    for (int i = 0; i < 2; i++)
        #pragma unroll
        for (int j = 0; j < 8; j++)
            #pragma unroll
            for (int t = 0; t < 4; t++) oc[i][j][t] = 0.f;

    for (int kt = 0; kt < N_ / KT; kt++) {
        cp_wait<1>();          // K(kt) done; V(kt) may still be in flight
        __syncthreads();

        // S = Q^T K  (bf16 wmma m16n16k16, fp32 accum) — overlaps V load
        {
            wmma::fragment<wmma::accumulator, 16, 16, 16, float> sacc[2][2];
            #pragma unroll
            for (int i = 0; i < 2; i++)
                #pragma unroll
                for (int j = 0; j < 2; j++) wmma::fill_fragment(sacc[i][j], 0.0f);

            #pragma unroll
            for (int kk = 0; kk < HD; kk += 16) {
                wmma::fragment<wmma::matrix_a, 16, 16, 16, __nv_bfloat16,
                               wmma::col_major> af[2];
                wmma::fragment<wmma::matrix_b, 16, 16, 16, __nv_bfloat16,
                               wmma::row_major> bf[2];
                #pragma unroll
                for (int i = 0; i < 2; i++)
                    wmma::load_matrix_sync(af[i], Qs + kk * QLH + wm * 32 + i * 16, QLH);
                #pragma unroll
                for (int j = 0; j < 2; j++)
                    wmma::load_matrix_sync(bf[j], Ks + kk * KLH + wn * 32 + j * 16, KLH);
                #pragma unroll
                for (int i = 0; i < 2; i++)
                    #pragma unroll
                    for (int j = 0; j < 2; j++)
                        wmma::mma_sync(sacc[i][j], af[i], bf[j], sacc[i][j]);
            }
            #pragma unroll
            for (int i = 0; i < 2; i++)
                #pragma unroll
                for (int j = 0; j < 2; j++) {
                    #pragma unroll
                    for (int t = 0; t < sacc[i][j].num_elements; t++)
                        sacc[i][j].x[t] *= scale;
                    wmma::store_matrix_sync(Ss + (wm * 32 + i * 16) * SL + wn * 32 + j * 16,
                                            sacc[i][j], SL, wmma::mem_row_major);
                }
        }
        __syncthreads();

        // Ks free: prefetch next K tile during softmax + PV
        if (kt + 1 < N_ / KT) issue_K((kt + 1) * KT);

        // online softmax; P (bf16) written over the same Ss rows.
        {
            const int r    = tid >> 1;
            const int half = tid & 1;
            float* row = Ss + r * SL + half * 32;
            __nv_bfloat16* prow = SpA + r * (SL * 2) + half * 32;
            float4 v[8];
            float mx = -1e30f;
            #pragma unroll
            for (int i = 0; i < 8; i++) {
                v[i] = *reinterpret_cast<const float4*>(row + i * 4);
                mx = fmaxf(mx, fmaxf(fmaxf(v[i].x, v[i].y), fmaxf(v[i].z, v[i].w)));
            }
            mx = fmaxf(mx, __shfl_xor_sync(0xffffffffu, mx, 1));
            const float mo = Ms[r];
            const float mn = fmaxf(mo, mx);
            const float alpha = __expf(mo - mn);
            float s = 0.f;
            #pragma unroll
            for (int i = 0; i < 8; i++) {
                v[i].x = __expf(v[i].x - mn); v[i].y = __expf(v[i].y - mn);
                v[i].z = __expf(v[i].z - mn); v[i].w = __expf(v[i].w - mn);
                s += v[i].x + v[i].y + v[i].z + v[i].w;
                uint2 p;
                p.x = bf2_bits(__floats2bfloat162_rn(v[i].x, v[i].y));
                p.y = bf2_bits(__floats2bfloat162_rn(v[i].z, v[i].w));
                *reinterpret_cast<uint2*>(prow + i * 4) = p;
            }
            s += __shfl_xor_sync(0xffffffffu, s, 1);
            if (half == 0) {
                Ms[r] = mn;
                Ls[r] = Ls[r] * alpha + s;
                Al[r] = alpha;
            }
        }
        cp_wait<1>();          // V(kt) done (K(kt+1) may remain in flight)
        __syncthreads();

        // rescale O by alpha, then O^T += V @ P^T  (bf16 m16n8k16)
        {
            const int qb = wn * 64;
            #pragma unroll
            for (int j = 0; j < 8; j++) {
                const float aE = Al[qb + j * 8 + 2 * tig];
                const float aO = Al[qb + j * 8 + 2 * tig + 1];
                #pragma unroll
                for (int i = 0; i < 2; i++) {
                    oc[i][j][0] *= aE; oc[i][j][1] *= aO;
                    oc[i][j][2] *= aE; oc[i][j][3] *= aO;
                }
            }
            #pragma unroll
            for (int kk = 0; kk < KT; kk += 16) {
                unsigned b0[8], b1[8];
                #pragma unroll
                for (int j = 0; j < 8; j++) {
                    const __nv_bfloat16* pr2 = SpA + (qb + j * 8 + g) * (SL * 2) + kk;
                    b0[j] = *reinterpret_cast<const unsigned*>(pr2 + 2 * tig);
                    b1[j] = *reinterpret_cast<const unsigned*>(pr2 + 8 + 2 * tig);
                }
                #pragma unroll
                for (int i = 0; i < 2; i++) {
                    const int dr = wm * 32 + i * 16;
                    const __nv_bfloat16* vr0 = Vs + (dr + g) * KLH + kk;
                    const __nv_bfloat16* vr1 = Vs + (dr + g + 8) * KLH + kk;
                    unsigned a0 = *reinterpret_cast<const unsigned*>(vr0 + 2 * tig);
                    unsigned a1 = *reinterpret_cast<const unsigned*>(vr1 + 2 * tig);
                    unsigned a2 = *reinterpret_cast<const unsigned*>(vr0 + 8 + 2 * tig);
                    unsigned a3 = *reinterpret_cast<const unsigned*>(vr1 + 8 + 2 * tig);
                    #pragma unroll
                    for (int j = 0; j < 8; j++)
                        mma_bf16(oc[i][j][0], oc[i][j][1], oc[i][j][2], oc[i][j][3],
                                 a0, a1, a2, a3, b0[j], b1[j]);
                }
            }
        }
        __syncthreads();       // PV done reading Vs; safe to refill V

        if (kt + 1 < N_ / KT) issue_V((kt + 1) * KT);
    }

    // final: /l, store O^T as bf16 pairs
    {
        const int qb = wn * 64;
        #pragma unroll
        for (int j = 0; j < 8; j++) {
            const int qc = qb + j * 8 + 2 * tig;
            const float iE = 1.0f / Ls[qc];
            const float iO = 1.0f / Ls[qc + 1];
            #pragma unroll
            for (int i = 0; i < 2; i++) {
                const int dr = wm * 32 + i * 16;
                __nv_bfloat162 lo = __floats2bfloat162_rn(oc[i][j][0] * iE, oc[i][j][1] * iO);
                __nv_bfloat162 hi = __floats2bfloat162_rn(oc[i][j][2] * iE, oc[i][j][3] * iO);
                *reinterpret_cast<__nv_bfloat162*>(Og + (long)(dr + g) * N_ + qc) = lo;
                *reinterpret_cast<__nv_bfloat162*>(Og + (long)(dr + g + 8) * N_ + qc) = hi;
            }
        }
    }
}

// ---------------------------------------------------------------------------
// Launch
// ---------------------------------------------------------------------------
extern "C" void kernel_launch(void* const* d_in, const int* in_sizes, int n_in,
                              void* d_out, int out_size)
{
    const float* x      = (const float*)d_in[0];
    const float* norm_w = (const float*)d_in[1];
    const float* norm_b = (const float*)d_in[2];
    const float* qkv_w  = (const float*)d_in[3];
    const float* qkv_b  = (const float*)d_in[4];
    const float* proj_w = (const float*)d_in[5];
    const float* proj_b = (const float*)d_in[6];
    float* out          = (float*)d_out;

    __nv_bfloat16 *y, *o, *wq, *wp, *qkv;
    cudaGetSymbolAddress((void**)&y,   g_y_bf);
    cudaGetSymbolAddress((void**)&qkv, g_qkv);
    cudaGetSymbolAddress((void**)&o,   g_o_bf);
    cudaGetSymbolAddress((void**)&wq,  g_wq_bf);
    cudaGetSymbolAddress((void**)&wp,  g_wp_bf);

    // Idempotent attribute setup (not stream ops; safe under graph capture)
    cudaFuncSetAttribute(flash_kernel,
                         cudaFuncAttributeMaxDynamicSharedMemorySize,
                         FLASH_SMEM_BYTES);
    cudaFuncSetAttribute(hgemm<1, true>,
                         cudaFuncAttributeMaxDynamicSharedMemorySize, TSM_BYTES);
    cudaFuncSetAttribute(hgemm<2, false>,
                         cudaFuncAttributeMaxDynamicSharedMemorySize, TSM_BYTES);

    // 1) GroupNorm + weight conversion (single launch)
    prep_kernel<<<B_ * GROUPS + 1024, 256>>>(x, norm_w, norm_b, y,
                                             qkv_w, wq, proj_w, wp);

    // 2) QKV (bf16 -> bf16): qkv[b] = wq @ y[b] + qkv_b
    {
        dim3 grid(N_ / TBN, QKV_C / TBM, B_);
        hgemm<1, true><<<grid, 256, TSM_BYTES>>>(
            wq, y, qkv, QKV_C, C_, N_,
            (long)C_ * N_, (long)QKV_C * N_, qkv_b, nullptr, 0);
    }

    // 3) Fused attention (2 CTAs/SM, split K/V waits) -> o
    {
        dim3 grid(N_ / QT, B_ * HEADS);
        flash_kernel<<<grid, 256, FLASH_SMEM_BYTES>>>(qkv, o);
    }

    // 4) out[b] = wp @ o[b] + proj_b + x[b]  (fp32 out)
    {
        dim3 grid(N_ / TBN, C_ / TBM, B_);
        hgemm<2, false><<<grid, 256, TSM_BYTES>>>(
            wp, o, out, C_, C_, N_,
            (long)C_ * N_, (long)C_ * N_, proj_b, x, (long)C_ * N_);
    }
}

// round 17
// speedup vs baseline: 1.0998x; 1.0099x over previous
#include <cuda_runtime.h>
#include <cuda_bf16.h>
#include <mma.h>
#include <math.h>
#include <string.h>

using namespace nvcuda;

// ---------------------------------------------------------------------------
// Shapes (fixed): x (16, 512, 32, 32) -> B=16, C=512, N=1024; heads=4, hd=128
// ---------------------------------------------------------------------------
#define B_   16
#define C_   512
#define N_   1024
#define HEADS 4
#define HD   128
#define GROUPS 32
#define GSIZE (C_ / GROUPS)
#define QKV_C (3 * C_)

// Scratch (device globals — allocation-free per harness rules)
__device__ __nv_bfloat16 g_y_bf [(size_t)B_ * C_ * N_];
__device__ __nv_bfloat16 g_qkv  [(size_t)B_ * QKV_C * N_];
__device__ __nv_bfloat16 g_o_bf [(size_t)B_ * C_ * N_];
__device__ __nv_bfloat16 g_wq_bf[(size_t)QKV_C * C_];
__device__ __nv_bfloat16 g_wp_bf[(size_t)C_ * C_];

// ---------------------------------------------------------------------------
// helpers
// ---------------------------------------------------------------------------
__device__ __forceinline__ unsigned bf2_bits(__nv_bfloat162 v)
{
    unsigned u; memcpy(&u, &v, 4); return u;
}
__device__ __forceinline__ void cp_async16(void* smem_dst, const void* gmem_src)
{
    unsigned s = (unsigned)__cvta_generic_to_shared(smem_dst);
    asm volatile("cp.async.cg.shared.global [%0], [%1], 16;\n" :: "r"(s), "l"(gmem_src));
}
__device__ __forceinline__ void cp_commit() { asm volatile("cp.async.commit_group;\n"); }
template<int N> __device__ __forceinline__ void cp_wait()
{ asm volatile("cp.async.wait_group %0;\n" :: "n"(N)); }

// ---------------------------------------------------------------------------
// Fused prep: GroupNorm (blocks 0..511, float4-vectorized) + weight bf16
// conversion (blocks 512..1279 -> qkv_w, 1280..1535 -> proj_w). One launch.
// ---------------------------------------------------------------------------
__global__ void prep_kernel(const float* __restrict__ x,
                            const float* __restrict__ w,
                            const float* __restrict__ bias,
                            __nv_bfloat16* __restrict__ y,
                            const float* __restrict__ qkv_w,
                            __nv_bfloat16* __restrict__ wq,
                            const float* __restrict__ proj_w,
                            __nv_bfloat16* __restrict__ wp)
{
    const int blk = blockIdx.x;
    if (blk >= B_ * GROUPS) {
        // weight conversion branch: one f4 per thread
        const int cb = blk - B_ * GROUPS;       // 0..1023
        const float* src;
        __nv_bfloat16* dst;
        int i;
        if (cb < 768) { src = qkv_w;  dst = wq; i = cb * 256 + threadIdx.x; }
        else          { src = proj_w; dst = wp; i = (cb - 768) * 256 + threadIdx.x; }
        float4 v = *reinterpret_cast<const float4*>(src + (size_t)i * 4);
        *reinterpret_cast<__nv_bfloat162*>(dst + (size_t)i * 4)     = __floats2bfloat162_rn(v.x, v.y);
        *reinterpret_cast<__nv_bfloat162*>(dst + (size_t)i * 4 + 2) = __floats2bfloat162_rn(v.z, v.w);
        return;
    }

    // GroupNorm branch (float4-vectorized). Group = 16 channels x 1024 = 4096 f4.
    const int g   = blk % GROUPS;
    const long base = (long)blk * (GSIZE * N_);
    const float4* xp4 = reinterpret_cast<const float4*>(x + base);
    __nv_bfloat16* yp = y + base;

    const int tid = threadIdx.x;
    float s = 0.f, s2 = 0.f;
    #pragma unroll 4
    for (int i = tid; i < GSIZE * N_ / 4; i += 256) {
        float4 v = xp4[i];
        s  += (v.x + v.y) + (v.z + v.w);
        s2 += (v.x * v.x + v.y * v.y) + (v.z * v.z + v.w * v.w);
    }
    __shared__ float rs[32], rs2[32];
    for (int off = 16; off > 0; off >>= 1) {
        s  += __shfl_down_sync(0xffffffffu, s,  off);
        s2 += __shfl_down_sync(0xffffffffu, s2, off);
    }
    if ((tid & 31) == 0) { rs[tid >> 5] = s; rs2[tid >> 5] = s2; }
    __syncthreads();
    if (tid < 32) {
        s  = (tid < 8) ? rs[tid]  : 0.f;
        s2 = (tid < 8) ? rs2[tid] : 0.f;
        for (int off = 4; off > 0; off >>= 1) {
            s  += __shfl_down_sync(0xffffffffu, s,  off);
            s2 += __shfl_down_sync(0xffffffffu, s2, off);
        }
        if (tid == 0) { rs[0] = s; rs2[0] = s2; }
    }
    __syncthreads();
    const float inv_n = 1.0f / (GSIZE * N_);
    const float mean  = rs[0] * inv_n;
    const float var   = rs2[0] * inv_n - mean * mean;
    const float rstd  = rsqrtf(var + 1e-5f);

    const int c0 = g * GSIZE;
    #pragma unroll 4
    for (int i = tid; i < GSIZE * N_ / 4; i += 256) {
        int ch = c0 + (i >> 8);                 // 256 f4 per channel
        const float a = rstd * w[ch];
        const float b = bias[ch] - mean * a;
        float4 v = xp4[i];
        uint2 p;
        p.x = bf2_bits(__floats2bfloat162_rn(v.x * a + b, v.y * a + b));
        p.y = bf2_bits(__floats2bfloat162_rn(v.z * a + b, v.w * a + b));
        *reinterpret_cast<uint2*>(yp + (size_t)i * 4) = p;
    }
}

// ---------------------------------------------------------------------------
// 2-stage cp.async BF16 wmma GEMM (R11-proven config):
//   C[z] = A(MxK bf16) @ B[z](KxN bf16) + bias[m] (+ R[z] fp32)
// BM=128, BN=128, BK=32. 8 warps 2m x 4n; warp tile 64x32.
// ---------------------------------------------------------------------------
#define TBM 128
#define TBN 128
#define TBK 32
#define TLDA 40
#define TLDB 136
#define TSTG_BYTES (TBM * TLDA * 2 + TBK * TLDB * 2)  // 18944
#define TSM_BYTES  (TBM * (TBN + 4) * 4)              // 67584 > 2*18944

template<int EPI, bool OUTB>   // EPI 1: +bias   2: +bias +residual
__global__ void __launch_bounds__(256, 2)
hgemm(const __nv_bfloat16* __restrict__ A, const __nv_bfloat16* __restrict__ B,
      void* __restrict__ Cv, int M, int K, int Nn,
      long sB, long sC, const float* __restrict__ bias,
      const float* __restrict__ R, long sR)
{
    extern __shared__ char smraw[];
    const int z = blockIdx.z;
    B += (long)z * sB;
    if (EPI == 2) R += (long)z * sR;

    const int tid = threadIdx.x;
    const int w   = tid >> 5;
    const int wm  = w >> 2;
    const int wn  = w & 3;
    const int m0  = blockIdx.y * TBM;
    const int n0  = blockIdx.x * TBN;

    auto issue_tile = [&](int k0, int st) {
        __nv_bfloat16* As = (__nv_bfloat16*)(smraw + st * TSTG_BYTES);
        __nv_bfloat16* Bs = As + TBM * TLDA;
        #pragma unroll
        for (int it = 0; it < 2; it++) {
            int id = tid + it * 256;
            int r = id >> 2, c = (id & 3) * 8;
            cp_async16(As + r * TLDA + c, A + (long)(m0 + r) * K + k0 + c);
        }
        #pragma unroll
        for (int it = 0; it < 2; it++) {
            int id = tid + it * 256;
            int r = id >> 4, c = (id & 15) * 8;
            cp_async16(Bs + r * TLDB + c, B + (long)(k0 + r) * Nn + n0 + c);
        }
        cp_commit();
    };

    wmma::fragment<wmma::accumulator, 16, 16, 16, float> acc[4][2];
    #pragma unroll
    for (int i = 0; i < 4; i++)
        #pragma unroll
        for (int j = 0; j < 2; j++) wmma::fill_fragment(acc[i][j], 0.0f);

    const int tiles = K / TBK;
    issue_tile(0, 0);

    for (int t = 0; t < tiles; t++) {
        if (t + 1 < tiles) { issue_tile((t + 1) * TBK, (t + 1) & 1); cp_wait<1>(); }
        else               { cp_wait<0>(); }
        __syncthreads();

        const __nv_bfloat16* As = (const __nv_bfloat16*)(smraw + (t & 1) * TSTG_BYTES);
        const __nv_bfloat16* Bs = As + TBM * TLDA;
        #pragma unroll
        for (int ks = 0; ks < 2; ks++) {
            const int kk = ks * 16;
            wmma::fragment<wmma::matrix_a, 16, 16, 16, __nv_bfloat16,
                           wmma::row_major> af[4];
            wmma::fragment<wmma::matrix_b, 16, 16, 16, __nv_bfloat16,
                           wmma::row_major> bfr[2];
            #pragma unroll
            for (int i = 0; i < 4; i++)
                wmma::load_matrix_sync(af[i], As + (wm * 64 + i * 16) * TLDA + kk, TLDA);
            #pragma unroll
            for (int j = 0; j < 2; j++)
                wmma::load_matrix_sync(bfr[j], Bs + kk * TLDB + wn * 32 + j * 16, TLDB);
            #pragma unroll
            for (int i = 0; i < 4; i++)
                #pragma unroll
                for (int j = 0; j < 2; j++)
                    wmma::mma_sync(acc[i][j], af[i], bfr[j], acc[i][j]);
        }
        __syncthreads();
    }

    float* St = (float*)smraw;
    constexpr int ldS = TBN + 4;
    #pragma unroll
    for (int i = 0; i < 4; i++)
        #pragma unroll
        for (int j = 0; j < 2; j++)
            wmma::store_matrix_sync(St + (wm * 64 + i * 16) * ldS + wn * 32 + j * 16,
                                    acc[i][j], ldS, wmma::mem_row_major);
    __syncthreads();
    #pragma unroll
    for (int i = tid; i < TBM * (TBN / 4); i += 256) {
        int r = i >> 5, c = (i & 31) * 4;
        int gm = m0 + r, gn = n0 + c;
        float4 v = *reinterpret_cast<const float4*>(St + r * ldS + c);
        float bv = bias[gm];
        v.x += bv; v.y += bv; v.z += bv; v.w += bv;
        if (EPI == 2) {
            float4 rv = *reinterpret_cast<const float4*>(R + (long)gm * Nn + gn);
            v.x += rv.x; v.y += rv.y; v.z += rv.z; v.w += rv.w;
        }
        if (OUTB) {
            __nv_bfloat16* C = (__nv_bfloat16*)Cv + (long)z * sC;
            uint2 p;
            p.x = bf2_bits(__floats2bfloat162_rn(v.x, v.y));
            p.y = bf2_bits(__floats2bfloat162_rn(v.z, v.w));
            *reinterpret_cast<uint2*>(C + (long)gm * Nn + gn) = p;
        } else {
            float* C = (float*)Cv + (long)z * sC;
            *reinterpret_cast<float4*>(C + (long)gm * Nn + gn) = v;
        }
    }
}

// ---------------------------------------------------------------------------
// Fused flash attention, 2 CTAs/SM, split K/V cp.async waits (as R16)
// ---------------------------------------------------------------------------
#define QT 128
#define KT 64
#define QLH 136                 // Q smem row (bf16 elems)
#define KLH 72                  // K/V smem row (bf16 elems)
#define SL  68                  // Ss fp32 row (bf16 row stride = 136)

#define OFB_Q  0
#define OFB_K  (OFB_Q + HD * QLH * 2)       // 34816
#define OFB_V  (OFB_K + HD * KLH * 2)       // 53248
#define OFB_SS (OFB_V + HD * KLH * 2)       // 71680
#define OFB_M  (OFB_SS + QT * SL * 4)       // 106496
#define OFB_L  (OFB_M + QT * 4)
#define OFB_A  (OFB_L + QT * 4)
#define FLASH_SMEM_BYTES (OFB_A + QT * 4)   // 108032 (105.5 KB) -> 2 CTAs/SM

__device__ __forceinline__ void mma_bf16(float& c0, float& c1, float& c2, float& c3,
                                         unsigned a0, unsigned a1, unsigned a2, unsigned a3,
                                         unsigned b0, unsigned b1)
{
    asm volatile(
        "mma.sync.aligned.m16n8k16.row.col.f32.bf16.bf16.f32 "
        "{%0,%1,%2,%3}, {%4,%5,%6,%7}, {%8,%9}, {%0,%1,%2,%3};\n"
        : "+f"(c0), "+f"(c1), "+f"(c2), "+f"(c3)
        : "r"(a0), "r"(a1), "r"(a2), "r"(a3), "r"(b0), "r"(b1));
}

__global__ void __launch_bounds__(256, 2)
flash_kernel(const __nv_bfloat16* __restrict__ qkv, __nv_bfloat16* __restrict__ o)
{
    extern __shared__ char smc[];
    __nv_bfloat16* Qs = (__nv_bfloat16*)(smc + OFB_Q);
    __nv_bfloat16* Ks = (__nv_bfloat16*)(smc + OFB_K);
    __nv_bfloat16* Vs = (__nv_bfloat16*)(smc + OFB_V);
    float*         Ss = (float*)(smc + OFB_SS);
    __nv_bfloat16* SpA = (__nv_bfloat16*)(smc + OFB_SS);  // P aliases Ss
    float*         Ms = (float*)(smc + OFB_M);
    float*         Ls = (float*)(smc + OFB_L);
    float*         Al = (float*)(smc + OFB_A);

    const int tid  = threadIdx.x;
    const int w    = tid >> 5;
    const int lane = tid & 31;
    const int g    = lane >> 2;
    const int tig  = lane & 3;
    const int wm   = w >> 1;
    const int wn   = w & 1;

    const int q0 = blockIdx.x * QT;
    const int bh = blockIdx.y;
    const long base = ((long)(bh >> 2) * QKV_C + (long)(bh & 3) * HD) * N_;
    const __nv_bfloat16* Qg = qkv + base;
    const __nv_bfloat16* Kg = qkv + base + (long)C_ * N_;
    const __nv_bfloat16* Vg = qkv + base + 2L * (long)C_ * N_;
    __nv_bfloat16* Og = o + ((long)(bh >> 2) * C_ + (long)(bh & 3) * HD) * N_ + q0;

    const float scale = 0.08838834764831845f;

    const int pr = tid >> 3, pc = (tid & 7) * 8;

    auto issue_K = [&](int k0) {
        #pragma unroll
        for (int it = 0; it < 4; it++) {
            int r = pr + it * 32;
            cp_async16(Ks + r * KLH + pc, Kg + (long)r * N_ + k0 + pc);
        }
        cp_commit();
    };
    auto issue_V = [&](int k0) {
        #pragma unroll
        for (int it = 0; it < 4; it++) {
            int r = pr + it * 32;
            cp_async16(Vs + r * KLH + pc, Vg + (long)r * N_ + k0 + pc);
        }
        cp_commit();
    };

    #pragma unroll
    for (int i = tid; i < HD * 16; i += 256) {
        int r = i >> 4, c = (i & 15) * 8;
        *reinterpret_cast<uint4*>(Qs + r * QLH + c) =
            *reinterpret_cast<const uint4*>(Qg + (long)r * N_ + q0 + c);
    }
    if (tid < QT) { Ms[tid] = -1e30f; Ls[tid] = 0.f; }
    issue_K(0);
    issue_V(0);

    float oc[2][8][4];
    #pragma unroll
    for (int i = 0; i < 2; i++)
        #pragma unroll
        for (int j = 0; j < 8; j++)
            #pragma unroll
            for (int t = 0; t < 4; t++) oc[i][j][t] = 0.f;

    for (int kt = 0; kt < N_ / KT; kt++) {
        cp_wait<1>();          // K(kt) done; V(kt) may still be in flight
        __syncthreads();

        // S = Q^T K  — overlaps the V load
        {
            wmma::fragment<wmma::accumulator, 16, 16, 16, float> sacc[2][2];
            #pragma unroll
            for (int i = 0; i < 2; i++)
                #pragma unroll
                for (int j = 0; j < 2; j++) wmma::fill_fragment(sacc[i][j], 0.0f);

            #pragma unroll
            for (int kk = 0; kk < HD; kk += 16) {
                wmma::fragment<wmma::matrix_a, 16, 16, 16, __nv_bfloat16,
                               wmma::col_major> af[2];
                wmma::fragment<wmma::matrix_b, 16, 16, 16, __nv_bfloat16,
                               wmma::row_major> bf[2];
                #pragma unroll
                for (int i = 0; i < 2; i++)
                    wmma::load_matrix_sync(af[i], Qs + kk * QLH + wm * 32 + i * 16, QLH);
                #pragma unroll
                for (int j = 0; j < 2; j++)
                    wmma::load_matrix_sync(bf[j], Ks + kk * KLH + wn * 32 + j * 16, KLH);
                #pragma unroll
                for (int i = 0; i < 2; i++)
                    #pragma unroll
                    for (int j = 0; j < 2; j++)
                        wmma::mma_sync(sacc[i][j], af[i], bf[j], sacc[i][j]);
            }
            #pragma unroll
            for (int i = 0; i < 2; i++)
                #pragma unroll
                for (int j = 0; j < 2; j++) {
                    #pragma unroll
                    for (int t = 0; t < sacc[i][j].num_elements; t++)
                        sacc[i][j].x[t] *= scale;
                    wmma::store_matrix_sync(Ss + (wm * 32 + i * 16) * SL + wn * 32 + j * 16,
                                            sacc[i][j], SL, wmma::mem_row_major);
                }
        }
        __syncthreads();

        if (kt + 1 < N_ / KT) issue_K((kt + 1) * KT);

        // online softmax; P (bf16) overwrites the Ss rows
        {
            const int r    = tid >> 1;
            const int half = tid & 1;
            float* row = Ss + r * SL + half * 32;
            __nv_bfloat16* prow = SpA + r * (SL * 2) + half * 32;
            float4 v[8];
            float mx = -1e30f;
            #pragma unroll
            for (int i = 0; i < 8; i++) {
                v[i] = *reinterpret_cast<const float4*>(row + i * 4);
                mx = fmaxf(mx, fmaxf(fmaxf(v[i].x, v[i].y), fmaxf(v[i].z, v[i].w)));
            }
            mx = fmaxf(mx, __shfl_xor_sync(0xffffffffu, mx, 1));
            const float mo = Ms[r];
            const float mn = fmaxf(mo, mx);
            const float alpha = __expf(mo - mn);
            float s = 0.f;
            #pragma unroll
            for (int i = 0; i < 8; i++) {
                v[i].x = __expf(v[i].x - mn); v[i].y = __expf(v[i].y - mn);
                v[i].z = __expf(v[i].z - mn); v[i].w = __expf(v[i].w - mn);
                s += v[i].x + v[i].y + v[i].z + v[i].w;
                uint2 p;
                p.x = bf2_bits(__floats2bfloat162_rn(v[i].x, v[i].y));
                p.y = bf2_bits(__floats2bfloat162_rn(v[i].z, v[i].w));
                *reinterpret_cast<uint2*>(prow + i * 4) = p;
            }
            s += __shfl_xor_sync(0xffffffffu, s, 1);
            if (half == 0) {
                Ms[r] = mn;
                Ls[r] = Ls[r] * alpha + s;
                Al[r] = alpha;
            }
        }
        cp_wait<1>();          // V(kt) done (K(kt+1) may remain in flight)
        __syncthreads();

        // rescale O, then O^T += V @ P^T
        {
            const int qb = wn * 64;
            #pragma unroll
            for (int j = 0; j < 8; j++) {
                const float aE = Al[qb + j * 8 + 2 * tig];
                const float aO = Al[qb + j * 8 + 2 * tig + 1];
                #pragma unroll
                for (int i = 0; i < 2; i++) {
                    oc[i][j][0] *= aE; oc[i][j][1] *= aO;
                    oc[i][j][2] *= aE; oc[i][j][3] *= aO;
                }
            }
            #pragma unroll
            for (int kk = 0; kk < KT; kk += 16) {
                unsigned b0[8], b1[8];
                #pragma unroll
                for (int j = 0; j < 8; j++) {
                    const __nv_bfloat16* pr2 = SpA + (qb + j * 8 + g) * (SL * 2) + kk;
                    b0[j] = *reinterpret_cast<const unsigned*>(pr2 + 2 * tig);
                    b1[j] = *reinterpret_cast<const unsigned*>(pr2 + 8 + 2 * tig);
                }
                #pragma unroll
                for (int i = 0; i < 2; i++) {
                    const int dr = wm * 32 + i * 16;
                    const __nv_bfloat16* vr0 = Vs + (dr + g) * KLH + kk;
                    const __nv_bfloat16* vr1 = Vs + (dr + g + 8) * KLH + kk;
                    unsigned a0 = *reinterpret_cast<const unsigned*>(vr0 + 2 * tig);
                    unsigned a1 = *reinterpret_cast<const unsigned*>(vr1 + 2 * tig);
                    unsigned a2 = *reinterpret_cast<const unsigned*>(vr0 + 8 + 2 * tig);
                    unsigned a3 = *reinterpret_cast<const unsigned*>(vr1 + 8 + 2 * tig);
                    #pragma unroll
                    for (int j = 0; j < 8; j++)
                        mma_bf16(oc[i][j][0], oc[i][j][1], oc[i][j][2], oc[i][j][3],
                                 a0, a1, a2, a3, b0[j], b1[j]);
                }
            }
        }
        __syncthreads();       // PV done reading Vs; safe to refill V

        if (kt + 1 < N_ / KT) issue_V((kt + 1) * KT);
    }

    // final: /l, store O^T as bf16 pairs
    {
        const int qb = wn * 64;
        #pragma unroll
        for (int j = 0; j < 8; j++) {
            const int qc = qb + j * 8 + 2 * tig;
            const float iE = 1.0f / Ls[qc];
            const float iO = 1.0f / Ls[qc + 1];
            #pragma unroll
            for (int i = 0; i < 2; i++) {
                const int dr = wm * 32 + i * 16;
                __nv_bfloat162 lo = __floats2bfloat162_rn(oc[i][j][0] * iE, oc[i][j][1] * iO);
                __nv_bfloat162 hi = __floats2bfloat162_rn(oc[i][j][2] * iE, oc[i][j][3] * iO);
                *reinterpret_cast<__nv_bfloat162*>(Og + (long)(dr + g) * N_ + qc) = lo;
                *reinterpret_cast<__nv_bfloat162*>(Og + (long)(dr + g + 8) * N_ + qc) = hi;
            }
        }
    }
}

// ---------------------------------------------------------------------------
// Launch
// ---------------------------------------------------------------------------
extern "C" void kernel_launch(void* const* d_in, const int* in_sizes, int n_in,
                              void* d_out, int out_size)
{
    const float* x      = (const float*)d_in[0];
    const float* norm_w = (const float*)d_in[1];
    const float* norm_b = (const float*)d_in[2];
    const float* qkv_w  = (const float*)d_in[3];
    const float* qkv_b  = (const float*)d_in[4];
    const float* proj_w = (const float*)d_in[5];
    const float* proj_b = (const float*)d_in[6];
    float* out          = (float*)d_out;

    __nv_bfloat16 *y, *o, *wq, *wp, *qkv;
    cudaGetSymbolAddress((void**)&y,   g_y_bf);
    cudaGetSymbolAddress((void**)&qkv, g_qkv);
    cudaGetSymbolAddress((void**)&o,   g_o_bf);
    cudaGetSymbolAddress((void**)&wq,  g_wq_bf);
    cudaGetSymbolAddress((void**)&wp,  g_wp_bf);

    // Idempotent attribute setup (not stream ops; safe under graph capture)
    cudaFuncSetAttribute(flash_kernel,
                         cudaFuncAttributeMaxDynamicSharedMemorySize,
                         FLASH_SMEM_BYTES);
    cudaFuncSetAttribute(hgemm<1, true>,
                         cudaFuncAttributeMaxDynamicSharedMemorySize, TSM_BYTES);
    cudaFuncSetAttribute(hgemm<2, false>,
                         cudaFuncAttributeMaxDynamicSharedMemorySize, TSM_BYTES);

    // 1) GroupNorm (vectorized) + weight conversion (single launch)
    prep_kernel<<<B_ * GROUPS + 1024, 256>>>(x, norm_w, norm_b, y,
                                             qkv_w, wq, proj_w, wp);

    // 2) QKV (bf16 -> bf16): qkv[b] = wq @ y[b] + qkv_b
    {
        dim3 grid(N_ / TBN, QKV_C / TBM, B_);
        hgemm<1, true><<<grid, 256, TSM_BYTES>>>(
            wq, y, qkv, QKV_C, C_, N_,
            (long)C_ * N_, (long)QKV_C * N_, qkv_b, nullptr, 0);
    }

    // 3) Fused attention (2 CTAs/SM, split K/V waits) -> o
    {
        dim3 grid(N_ / QT, B_ * HEADS);
        flash_kernel<<<grid, 256, FLASH_SMEM_BYTES>>>(qkv, o);
    }

    // 4) out[b] = wp @ o[b] + proj_b + x[b]  (fp32 out)
    {
        dim3 grid(N_ / TBN, C_ / TBM, B_);
        hgemm<2, false><<<grid, 256, TSM_BYTES>>>(
            wp, o, out, C_, C_, N_,
            (long)C_ * N_, (long)C_ * N_, proj_b, x, (long)C_ * N_);
    }
}